// round 10
// baseline (speedup 1.0000x reference)
#include <cuda_runtime.h>
#include <stdint.h>

#define NN     4096
#define FIN    256
#define NHEADS 4
#define FOUT_  64
#define CTOT   256
#define RB     8

// Scratch. g_h uses a PERMUTED channel layout per row:
//   storage index = i*16 + h*4 + w   for original channel c = h*64 + i*4 + w
// so that one warp-LDG.128 over lanes (r,h) touches 4 x 16B inside ONE 64B
// region (1 L1 wavefront) instead of 4 different 128B lines.
__device__ float  g_h [NN * CTOT];
__device__ float  g_e1[NN * NHEADS];
__device__ float  g_e2[NN * NHEADS];
__device__ float  g_gmax[NHEADS];
__device__ float2 g_aa[NN * NHEADS];   // {exp(e1-m), exp(0.2 e1-m)}
__device__ float2 g_bb[NN * NHEADS];   // {exp(e2),   exp(0.2 e2)}

__device__ __forceinline__ float lrelu(float s) { return fmaxf(s, 0.2f * s); }

__device__ __forceinline__ void ffma2(unsigned long long& d,
                                      unsigned long long a,
                                      unsigned long long b)
{
    asm("fma.rn.f32x2 %0, %1, %2, %0;" : "+l"(d) : "l"(a), "l"(b));
}
__device__ __forceinline__ unsigned long long dup2(float w)
{
    unsigned long long r;
    asm("mov.b64 %0, {%1, %1};" : "=l"(r) : "f"(w));
    return r;
}
union UF2 { unsigned long long u; float2 f; };

// ---------------------------------------------------------------------------
// Kernel 1: h = x @ W (permuted store), plus e1[n][h], e2[n][h].
// ---------------------------------------------------------------------------
__global__ __launch_bounds__(256) void k_proj(const float* __restrict__ x,
                                              const float* __restrict__ W,
                                              const float* __restrict__ a)
{
    const int t  = threadIdx.x;         // original output channel c = t
    const int n0 = blockIdx.x * 8;

    __shared__ float sx[8][FIN];
    {
        const float4* xs = (const float4*)(x + (size_t)n0 * FIN);
        float4* ss = (float4*)&sx[0][0];
        ss[t]       = xs[t];
        ss[t + 256] = xs[t + 256];
    }
    __syncthreads();

    float acc[8];
#pragma unroll
    for (int r = 0; r < 8; r++) acc[r] = 0.f;

#pragma unroll 4
    for (int k = 0; k < FIN; k++) {
        const float wv = W[k * CTOT + t];
#pragma unroll
        for (int r = 0; r < 8; r++) acc[r] += sx[r][k] * wv;
    }

    const int f  = t & 63;               // feature within head
    const int hh = t >> 6;               // head
    const float a1 = a[f];
    const float a2 = a[64 + f];
    const int dstc = (f >> 2) * 16 + hh * 4 + (f & 3);   // permuted channel

    __shared__ float red1[8], red2[8];
#pragma unroll
    for (int r = 0; r < 8; r++) {
        g_h[(size_t)(n0 + r) * CTOT + dstc] = acc[r];
        float p1 = acc[r] * a1;
        float p2 = acc[r] * a2;
#pragma unroll
        for (int o = 16; o; o >>= 1) {
            p1 += __shfl_xor_sync(0xffffffffu, p1, o);
            p2 += __shfl_xor_sync(0xffffffffu, p2, o);
        }
        if ((t & 31) == 0) { red1[t >> 5] = p1; red2[t >> 5] = p2; }
        __syncthreads();
        if (t < 4) {
            g_e1[(size_t)(n0 + r) * NHEADS + t] = red1[2 * t] + red1[2 * t + 1];
            g_e2[(size_t)(n0 + r) * NHEADS + t] = red2[2 * t] + red2[2 * t + 1];
        }
        __syncthreads();
    }
}

// ---------------------------------------------------------------------------
// Kernel 1b: global max of e2 per head.
// ---------------------------------------------------------------------------
__global__ __launch_bounds__(256) void k_gmax()
{
    const int t = threadIdx.x;
    const int h = t & 3;
    float m = -1e30f;
    for (int n = t >> 2; n < NN; n += 64)
        m = fmaxf(m, g_e2[n * NHEADS + h]);
    __shared__ float sm[256];
    sm[t] = m;
    __syncthreads();
    for (int s = 128; s >= 4; s >>= 1) {
        if (t < s) sm[t] = fmaxf(sm[t], sm[t + s]);
        __syncthreads();
    }
    if (t < 4) g_gmax[t] = sm[t];
}

// ---------------------------------------------------------------------------
// Kernel 1c: factored softmax terms, packed as float2.
//   m_i = lrelu(e1 + gmax) >= true masked row max (lrelu monotone).
// ---------------------------------------------------------------------------
__global__ __launch_bounds__(256) void k_prep()
{
    const int idx = blockIdx.x * 256 + threadIdx.x;   // node*NHEADS + head
    const int h   = idx & 3;
    const float e1 = g_e1[idx];
    const float e2 = g_e2[idx];
    const float gm = g_gmax[h];
    const float m  = lrelu(e1 + gm);
    g_aa[idx] = make_float2(__expf(e1 - m), __expf(0.2f * e1 - m));
    g_bb[idx] = make_float2(__expf(e2), __expf(0.2f * e2));
}

// ---------------------------------------------------------------------------
// Kernel 2: barrier-free masked softmax-aggregation.
//   lane = (r, h): r = lane>>2 (row 0..7), h = lane&3 (head).
//   Lane owns all 64 channels of head h for row i0+r (32 f32x2 accumulators).
//   Warp wrp streams j in [wrp*512, wrp*512+512). Per j: weight computed
//   in-register (2 FMUL + FMAX from factored terms), then 16 LDG.128 of h
//   (4-addr dedup within one 64B line) feed 32 FFMA2. No barriers in loop.
// ---------------------------------------------------------------------------
__global__ __launch_bounds__(256, 2) void k_attn(const int* __restrict__ adj,
                                                 float* __restrict__ out)
{
    const int t    = threadIdx.x;
    const int lane = t & 31;
    const int wrp  = t >> 5;
    const int i0   = blockIdx.x * RB;

    __shared__ unsigned amask[RB][NN / 32];   // 4 KB
    __shared__ float    zp[RB * 32];          // per-lane z partials, 1 KB
    __shared__ float    obuf[32][66];         // epilogue buffer (66: 8B-aligned rows)

    // adjacency -> bitmask (warp wrp <-> row i0+wrp)
    {
        const int* arow = adj + (size_t)(i0 + wrp) * NN;
#pragma unroll 4
        for (int b = 0; b < NN / 32; b++) {
            unsigned m = __ballot_sync(0xffffffffu, arow[b * 32 + lane] != 0);
            if (lane == 0) amask[wrp][b] = m;
        }
    }
    __syncthreads();

    const int r = lane >> 2;
    const int h = lane & 3;
    const float2 aa = g_aa[(size_t)(i0 + r) * NHEADS + h];

    unsigned long long acc[32];
#pragma unroll
    for (int k = 0; k < 32; k++) acc[k] = 0ull;
    float z = 0.f;

    const int j0 = wrp * (NN / 8);
    for (int jb = j0; jb < j0 + NN / 8; jb += 32) {
        const unsigned word = amask[r][jb >> 5];
#pragma unroll 4
        for (int q = 0; q < 32; q++) {
            const int j = jb + q;
            const float2 bb = g_bb[(size_t)j * NHEADS + h];
            float w = fmaxf(aa.x * bb.x, aa.y * bb.y);
            if (!((word >> q) & 1u)) w = 0.f;
            z += w;
            const unsigned long long ww = dup2(w);
            const ulonglong2* hp =
                (const ulonglong2*)(g_h + (size_t)j * CTOT + h * 4);
#pragma unroll
            for (int i = 0; i < 16; i++) {
                const ulonglong2 hv = hp[i * 4];   // 64B stride between chunks
                ffma2(acc[2 * i],     ww, hv.x);
                ffma2(acc[2 * i + 1], ww, hv.y);
            }
        }
    }

    zp[wrp * 32 + lane] = z;

    // Epilogue: for each row rr, gather 8 warp-partials, normalize, mean.
#pragma unroll
    for (int rr = 0; rr < RB; rr++) {
        __syncthreads();
        if (r == rr) {
            float2* dst = (float2*)&obuf[wrp * 4 + h][0];
#pragma unroll
            for (int k = 0; k < 32; k++) {
                UF2 u; u.u = acc[k];
                dst[k] = u.f;
            }
        }
        __syncthreads();
        if (t < FOUT_) {
            float inv[NHEADS];
#pragma unroll
            for (int hh = 0; hh < NHEADS; hh++) {
                float zz = 0.f;
#pragma unroll
                for (int w2 = 0; w2 < 8; w2++)
                    zz += zp[w2 * 32 + rr * 4 + hh];
                inv[hh] = 0.25f / zz;
            }
            float o = 0.f;
#pragma unroll
            for (int hh = 0; hh < NHEADS; hh++) {
                float s = 0.f;
#pragma unroll
                for (int w2 = 0; w2 < 8; w2++)
                    s += obuf[w2 * 4 + hh][t];
                o += s * inv[hh];
            }
            out[(size_t)(i0 + rr) * FOUT_ + t] = o;
        }
    }
}

// ---------------------------------------------------------------------------
extern "C" void kernel_launch(void* const* d_in, const int* in_sizes, int n_in,
                              void* d_out, int out_size)
{
    const float* x   = (const float*)d_in[0];   // 4096 x 256
    const int*   adj = (const int*)  d_in[1];   // 4096 x 4096
    const float* W   = (const float*)d_in[2];   // 256 x 256
    const float* a   = (const float*)d_in[3];   // 128 x 1
    float* out = (float*)d_out;                 // 4096 x 64

    (void)in_sizes; (void)n_in; (void)out_size;

    k_proj<<<NN / 8, 256>>>(x, W, a);
    k_gmax<<<1, 256>>>();
    k_prep<<<NN * NHEADS / 256, 256>>>();
    k_attn<<<NN / RB, 256>>>(adj, out);
}

// round 11
// speedup vs baseline: 6.3087x; 6.3087x over previous
#include <cuda_runtime.h>
#include <stdint.h>

#define NN     4096
#define FIN    256
#define NHEADS 4
#define FOUT_  64
#define CTOT   256
#define MI     64            // rows per attention CTA
#define SJ     2             // j-range splits
#define KJ     (NN / SJ)     // 2048 j per CTA
#define TILE   32
#define NTILES (KJ / TILE)   // 64
#define HPAD   264           // h_s row stride (j-stride = 8 mod 32 -> conflict-free B)

// Scratch
__device__ float  g_h [NN * CTOT];
__device__ float  g_e1[NN * NHEADS];
__device__ float  g_e2[NN * NHEADS];
__device__ float  g_gmax[NHEADS];
__device__ float2 g_aa[NN * NHEADS];          // {exp(e1-m), exp(0.2 e1-m)}
__device__ float2 g_bb[NN * NHEADS];          // {exp(e2),   exp(0.2 e2)}
__device__ float  g_part [SJ][NN][CTOT];      // numerator partials (8 MB)
__device__ float  g_zpart[SJ][NN][NHEADS];    // Z partials

__device__ __forceinline__ float lrelu(float s) { return fmaxf(s, 0.2f * s); }

__device__ __forceinline__ unsigned to_tf32(float x)
{
    unsigned u;
    asm("cvt.rna.tf32.f32 %0, %1;" : "=r"(u) : "f"(x));
    return u;
}

__device__ __forceinline__ void mma_tf32(float* c, const unsigned* a,
                                         unsigned b0, unsigned b1)
{
    asm("mma.sync.aligned.m16n8k8.row.col.f32.tf32.tf32.f32 "
        "{%0,%1,%2,%3}, {%4,%5,%6,%7}, {%8,%9}, {%0,%1,%2,%3};"
        : "+f"(c[0]), "+f"(c[1]), "+f"(c[2]), "+f"(c[3])
        : "r"(a[0]), "r"(a[1]), "r"(a[2]), "r"(a[3]), "r"(b0), "r"(b1));
}

// ---------------------------------------------------------------------------
// Kernel 1: h = x @ W (plain layout), plus e1[n][h], e2[n][h].
// ---------------------------------------------------------------------------
__global__ __launch_bounds__(256) void k_proj(const float* __restrict__ x,
                                              const float* __restrict__ W,
                                              const float* __restrict__ a)
{
    const int t  = threadIdx.x;
    const int n0 = blockIdx.x * 8;

    __shared__ float sx[8][FIN];
    {
        const float4* xs = (const float4*)(x + (size_t)n0 * FIN);
        float4* ss = (float4*)&sx[0][0];
        ss[t]       = xs[t];
        ss[t + 256] = xs[t + 256];
    }
    __syncthreads();

    float acc[8];
#pragma unroll
    for (int r = 0; r < 8; r++) acc[r] = 0.f;

#pragma unroll 4
    for (int k = 0; k < FIN; k++) {
        const float wv = W[k * CTOT + t];
#pragma unroll
        for (int r = 0; r < 8; r++) acc[r] += sx[r][k] * wv;
    }

    const int f = t & 63;
    const float a1 = a[f];
    const float a2 = a[64 + f];

    __shared__ float red1[8], red2[8];
#pragma unroll
    for (int r = 0; r < 8; r++) {
        g_h[(size_t)(n0 + r) * CTOT + t] = acc[r];
        float p1 = acc[r] * a1;
        float p2 = acc[r] * a2;
#pragma unroll
        for (int o = 16; o; o >>= 1) {
            p1 += __shfl_xor_sync(0xffffffffu, p1, o);
            p2 += __shfl_xor_sync(0xffffffffu, p2, o);
        }
        if ((t & 31) == 0) { red1[t >> 5] = p1; red2[t >> 5] = p2; }
        __syncthreads();
        if (t < 4) {
            g_e1[(size_t)(n0 + r) * NHEADS + t] = red1[2 * t] + red1[2 * t + 1];
            g_e2[(size_t)(n0 + r) * NHEADS + t] = red2[2 * t] + red2[2 * t + 1];
        }
        __syncthreads();
    }
}

// ---------------------------------------------------------------------------
// Kernel 1b: global max of e2 per head.
// ---------------------------------------------------------------------------
__global__ __launch_bounds__(256) void k_gmax()
{
    const int t = threadIdx.x;
    const int h = t & 3;
    float m = -1e30f;
    for (int n = t >> 2; n < NN; n += 64)
        m = fmaxf(m, g_e2[n * NHEADS + h]);
    __shared__ float sm[256];
    sm[t] = m;
    __syncthreads();
    for (int s = 128; s >= 4; s >>= 1) {
        if (t < s) sm[t] = fmaxf(sm[t], sm[t + s]);
        __syncthreads();
    }
    if (t < 4) g_gmax[t] = sm[t];
}

// ---------------------------------------------------------------------------
// Kernel 1c: factored softmax terms (exp only per NODE, not per edge).
//   m_i = lrelu(e1 + gmax) >= true masked row max (lrelu monotone).
// ---------------------------------------------------------------------------
__global__ __launch_bounds__(256) void k_prep()
{
    const int idx = blockIdx.x * 256 + threadIdx.x;   // node*NHEADS + head
    const int h   = idx & 3;
    const float e1 = g_e1[idx];
    const float e2 = g_e2[idx];
    const float gm = g_gmax[h];
    const float m  = lrelu(e1 + gm);
    g_aa[idx] = make_float2(__expf(e1 - m), __expf(0.2f * e1 - m));
    g_bb[idx] = make_float2(__expf(e2), __expf(0.2f * e2));
}

// ---------------------------------------------------------------------------
// Kernel 2: tensor-core masked softmax-aggregation (tf32 mma.sync).
//   CTA: 512 threads = 16 warps, 64 rows, j-range KJ (one of SJ splits).
//   Warp (rg = wid&3, hh = wid>>2): rows rg*16..+15, head hh, 64 channels.
//   Per 32-j tile: h staged tf32 in smem (stride 264: conflict-free B LDS),
//   P computed in-register from factored terms (no exp, no P smem), adjacency
//   ballot-masks prefetched one tile ahead. Accum fp32 in mma; Z in fp32.
// ---------------------------------------------------------------------------
__global__ __launch_bounds__(512, 1) void k_attn(const int* __restrict__ adj)
{
    const int t    = threadIdx.x;
    const int lane = t & 31;
    const int wid  = t >> 5;
    const int rg   = wid & 3;
    const int hh   = wid >> 2;
    const int r0   = lane >> 2;
    const int c0   = lane & 3;

    const int row0 = (blockIdx.x >> 1) * MI;
    const int js   = blockIdx.x & 1;
    const int jb0  = js * KJ;

    __shared__ float    h_s[TILE][HPAD];      // ~33 KB
    __shared__ float2   bb_s[TILE][NHEADS];   // 1 KB
    __shared__ unsigned mask_s[MI];           // 256 B
    __shared__ float    zred[MI][NHEADS];     // 1 KB

    const int rowA = row0 + rg * 16 + r0;     // this thread's first C row
    const float2 aa0 = g_aa[(size_t)rowA * NHEADS + hh];
    const float2 aa1 = g_aa[(size_t)(rowA + 8) * NHEADS + hh];

    float acc[8][4];
#pragma unroll
    for (int n = 0; n < 8; n++)
#pragma unroll
        for (int q = 0; q < 4; q++) acc[n][q] = 0.f;
    float z0 = 0.f, z1 = 0.f;

    // adjacency prefetch: warp wid covers rows row0 + wid*4 .. +3
    const int mrow = row0 + wid * 4;
    int av[4];
#pragma unroll
    for (int rr = 0; rr < 4; rr++)
        av[rr] = adj[(size_t)(mrow + rr) * NN + jb0 + lane];

    for (int tile = 0; tile < NTILES; tile++) {
        const int jb = jb0 + tile * TILE;
        __syncthreads();   // previous tile's compute finished

        // masks for this tile
#pragma unroll
        for (int rr = 0; rr < 4; rr++) {
            unsigned m = __ballot_sync(0xffffffffu, av[rr] != 0);
            if (lane == 0) mask_s[wid * 4 + rr] = m;
        }
        // prefetch next tile's adjacency
        if (tile + 1 < NTILES) {
#pragma unroll
            for (int rr = 0; rr < 4; rr++)
                av[rr] = adj[(size_t)(mrow + rr) * NN + jb + TILE + lane];
        }
        // stage h tile, rounded to tf32 (2048 float4, 4 per thread)
        {
            const float4* src = (const float4*)(g_h + (size_t)jb * CTOT);
#pragma unroll
            for (int q = 0; q < 4; q++) {
                const int f = t + q * 512;         // float4 id 0..2047
                float4 v = src[f];
                v.x = __uint_as_float(to_tf32(v.x));
                v.y = __uint_as_float(to_tf32(v.y));
                v.z = __uint_as_float(to_tf32(v.z));
                v.w = __uint_as_float(to_tf32(v.w));
                const int j = f >> 6;              // 64 float4 per 256-ch row
                const int c = (f & 63) * 4;
                *(float4*)&h_s[j][c] = v;
            }
        }
        // stage bb tile
        if (t < 128)
            bb_s[t >> 2][t & 3] = g_bb[(size_t)(jb + (t >> 2)) * NHEADS + (t & 3)];
        __syncthreads();

        const unsigned mw0 = mask_s[rg * 16 + r0];
        const unsigned mw1 = mask_s[rg * 16 + r0 + 8];

#pragma unroll
        for (int kc = 0; kc < 4; kc++) {
            const int k0  = kc * 8;
            const int jl0 = k0 + c0;
            const int jl1 = jl0 + 4;
            const float2 bb0 = bb_s[jl0][hh];
            const float2 bb1 = bb_s[jl1][hh];

            float w0 = fmaxf(aa0.x * bb0.x, aa0.y * bb0.y);
            float w1 = fmaxf(aa1.x * bb0.x, aa1.y * bb0.y);
            float w2 = fmaxf(aa0.x * bb1.x, aa0.y * bb1.y);
            float w3 = fmaxf(aa1.x * bb1.x, aa1.y * bb1.y);
            if (!((mw0 >> jl0) & 1u)) w0 = 0.f;
            if (!((mw1 >> jl0) & 1u)) w1 = 0.f;
            if (!((mw0 >> jl1) & 1u)) w2 = 0.f;
            if (!((mw1 >> jl1) & 1u)) w3 = 0.f;
            z0 += w0 + w2;
            z1 += w1 + w3;

            unsigned afr[4];
            afr[0] = to_tf32(w0);
            afr[1] = to_tf32(w1);
            afr[2] = to_tf32(w2);
            afr[3] = to_tf32(w3);

#pragma unroll
            for (int nt = 0; nt < 8; nt++) {
                const int n0 = hh * 64 + nt * 8 + r0;
                const unsigned b0 = __float_as_uint(h_s[jl0][n0]);
                const unsigned b1 = __float_as_uint(h_s[jl1][n0]);
                mma_tf32(acc[nt], afr, b0, b1);
            }
        }
    }

    // Z: reduce across the 4 lanes sharing a row (c0 = lane&3)
#pragma unroll
    for (int o = 1; o <= 2; o <<= 1) {
        z0 += __shfl_xor_sync(0xffffffffu, z0, o);
        z1 += __shfl_xor_sync(0xffffffffu, z1, o);
    }
    if (c0 == 0) {
        zred[rg * 16 + r0][hh]     = z0;
        zred[rg * 16 + r0 + 8][hh] = z1;
    }
    __syncthreads();
    if (t < MI * NHEADS)
        g_zpart[js][row0 + (t >> 2)][t & 3] = zred[t >> 2][t & 3];

    // numerator partials straight from accumulators
#pragma unroll
    for (int nt = 0; nt < 8; nt++) {
        const int cb = hh * 64 + nt * 8 + 2 * c0;
        *(float2*)&g_part[js][rowA][cb]     = make_float2(acc[nt][0], acc[nt][1]);
        *(float2*)&g_part[js][rowA + 8][cb] = make_float2(acc[nt][2], acc[nt][3]);
    }
}

// ---------------------------------------------------------------------------
// Kernel 3: combine j-splits, normalize by Z, mean over heads.
// ---------------------------------------------------------------------------
__global__ __launch_bounds__(256) void k_final(float* __restrict__ out)
{
    const int idx = blockIdx.x * 256 + threadIdx.x;   // row*64 + f
    const int row = idx >> 6;
    const int f   = idx & 63;
    float o = 0.f;
#pragma unroll
    for (int h = 0; h < NHEADS; h++) {
        const float num = g_part[0][row][h * 64 + f] + g_part[1][row][h * 64 + f];
        const float zz  = g_zpart[0][row][h] + g_zpart[1][row][h];
        o += num / zz;
    }
    out[idx] = 0.25f * o;
}

// ---------------------------------------------------------------------------
extern "C" void kernel_launch(void* const* d_in, const int* in_sizes, int n_in,
                              void* d_out, int out_size)
{
    const float* x   = (const float*)d_in[0];   // 4096 x 256
    const int*   adj = (const int*)  d_in[1];   // 4096 x 4096
    const float* W   = (const float*)d_in[2];   // 256 x 256
    const float* a   = (const float*)d_in[3];   // 128 x 1
    float* out = (float*)d_out;                 // 4096 x 64

    (void)in_sizes; (void)n_in; (void)out_size;

    k_proj<<<NN / 8, 256>>>(x, W, a);
    k_gmax<<<1, 256>>>();
    k_prep<<<NN * NHEADS / 256, 256>>>();
    k_attn<<<(NN / MI) * SJ, 512>>>(adj);
    k_final<<<NN * FOUT_ / 256, 256>>>(out);
}

// round 12
// speedup vs baseline: 7.8520x; 1.2446x over previous
#include <cuda_runtime.h>
#include <stdint.h>

#define NN     4096
#define FIN    256
#define NHEADS 4
#define FOUT_  64
#define CTOT   256
#define MI     64            // rows per attention CTA
#define SJ     2             // j-range splits
#define KJ     (NN / SJ)     // 2048 j per CTA
#define TILE   32
#define NTILES (KJ / TILE)   // 64
#define HPAD   264           // h_s row stride (mod 32 = 8 -> conflict-free B LDS)

// Scratch
__device__ float  g_h [NN * CTOT];            // tf32-pre-rounded
__device__ float  g_e1[NN * NHEADS];
__device__ float  g_e2[NN * NHEADS];
__device__ float  g_gmax[NHEADS];
__device__ float2 g_aa[NN * NHEADS];          // {exp(e1-m), exp(0.2 e1-m)}
__device__ float2 g_bb[NN * NHEADS];          // {exp(e2),   exp(0.2 e2)}
__device__ float  g_part [SJ][NN][CTOT];      // numerator partials (8 MB)
__device__ float  g_zpart[SJ][NN][NHEADS];    // Z partials

__device__ __forceinline__ float lrelu(float s) { return fmaxf(s, 0.2f * s); }

__device__ __forceinline__ unsigned to_tf32(float x)
{
    unsigned u;
    asm("cvt.rna.tf32.f32 %0, %1;" : "=r"(u) : "f"(x));
    return u;
}

__device__ __forceinline__ void mma_tf32(float* c, const unsigned* a,
                                         unsigned b0, unsigned b1)
{
    asm("mma.sync.aligned.m16n8k8.row.col.f32.tf32.tf32.f32 "
        "{%0,%1,%2,%3}, {%4,%5,%6,%7}, {%8,%9}, {%0,%1,%2,%3};"
        : "+f"(c[0]), "+f"(c[1]), "+f"(c[2]), "+f"(c[3])
        : "r"(a[0]), "r"(a[1]), "r"(a[2]), "r"(a[3]), "r"(b0), "r"(b1));
}

__device__ __forceinline__ void cp_async16(uint32_t smem_addr, const void* gptr)
{
    asm volatile("cp.async.cg.shared.global [%0], [%1], 16;"
                 :: "r"(smem_addr), "l"(gptr));
}

// ---------------------------------------------------------------------------
// Kernel 1: h = x @ W (stored pre-rounded to tf32), plus e1[n][h], e2[n][h].
// ---------------------------------------------------------------------------
__global__ __launch_bounds__(256) void k_proj(const float* __restrict__ x,
                                              const float* __restrict__ W,
                                              const float* __restrict__ a)
{
    const int t  = threadIdx.x;
    const int n0 = blockIdx.x * 8;

    __shared__ float sx[8][FIN];
    {
        const float4* xs = (const float4*)(x + (size_t)n0 * FIN);
        float4* ss = (float4*)&sx[0][0];
        ss[t]       = xs[t];
        ss[t + 256] = xs[t + 256];
    }
    __syncthreads();

    float acc[8];
#pragma unroll
    for (int r = 0; r < 8; r++) acc[r] = 0.f;

#pragma unroll 4
    for (int k = 0; k < FIN; k++) {
        const float wv = W[k * CTOT + t];
#pragma unroll
        for (int r = 0; r < 8; r++) acc[r] += sx[r][k] * wv;
    }

    const int f = t & 63;
    const float a1 = a[f];
    const float a2 = a[64 + f];

    __shared__ float red1[8], red2[8];
#pragma unroll
    for (int r = 0; r < 8; r++) {
        g_h[(size_t)(n0 + r) * CTOT + t] = __uint_as_float(to_tf32(acc[r]));
        float p1 = acc[r] * a1;
        float p2 = acc[r] * a2;
#pragma unroll
        for (int o = 16; o; o >>= 1) {
            p1 += __shfl_xor_sync(0xffffffffu, p1, o);
            p2 += __shfl_xor_sync(0xffffffffu, p2, o);
        }
        if ((t & 31) == 0) { red1[t >> 5] = p1; red2[t >> 5] = p2; }
        __syncthreads();
        if (t < 4) {
            g_e1[(size_t)(n0 + r) * NHEADS + t] = red1[2 * t] + red1[2 * t + 1];
            g_e2[(size_t)(n0 + r) * NHEADS + t] = red2[2 * t] + red2[2 * t + 1];
        }
        __syncthreads();
    }
}

// ---------------------------------------------------------------------------
// Kernel 1b: global max of e2 per head.
// ---------------------------------------------------------------------------
__global__ __launch_bounds__(256) void k_gmax()
{
    const int t = threadIdx.x;
    const int h = t & 3;
    float m = -1e30f;
    for (int n = t >> 2; n < NN; n += 64)
        m = fmaxf(m, g_e2[n * NHEADS + h]);
    __shared__ float sm[256];
    sm[t] = m;
    __syncthreads();
    for (int s = 128; s >= 4; s >>= 1) {
        if (t < s) sm[t] = fmaxf(sm[t], sm[t + s]);
        __syncthreads();
    }
    if (t < 4) g_gmax[t] = sm[t];
}

// ---------------------------------------------------------------------------
// Kernel 1c: factored softmax terms (exp per NODE, not per edge).
//   m_i = lrelu(e1 + gmax) >= true masked row max (lrelu monotone).
// ---------------------------------------------------------------------------
__global__ __launch_bounds__(256) void k_prep()
{
    const int idx = blockIdx.x * 256 + threadIdx.x;   // node*NHEADS + head
    const int h   = idx & 3;
    const float e1 = g_e1[idx];
    const float e2 = g_e2[idx];
    const float gm = g_gmax[h];
    const float m  = lrelu(e1 + gm);
    g_aa[idx] = make_float2(__expf(e1 - m), __expf(0.2f * e1 - m));
    g_bb[idx] = make_float2(__expf(e2), __expf(0.2f * e2));
}

// ---------------------------------------------------------------------------
// Kernel 2: tensor-core masked softmax-aggregation, cp.async double-buffered.
//   CTA: 512 threads = 16 warps. Warp (rg = wid&3, hh = wid>>2): 16 rows,
//   head hh. Per 32-j tile: h (pre-rounded tf32) + bb staged via cp.async
//   into ping-pong buffers; P computed in-register from factored terms;
//   adjacency ballot-masks prefetched one tile ahead in registers.
// ---------------------------------------------------------------------------
__global__ __launch_bounds__(512, 1) void k_attn(const int* __restrict__ adj)
{
    extern __shared__ float smem[];
    // layout: h_s[2][TILE][HPAD] | bb_s[2][TILE][NHEADS](float2) | mask | zred
    float*    h_s0   = smem;
    float2*   bb_s0  = (float2*)(smem + 2 * TILE * HPAD);
    unsigned* mask_s = (unsigned*)(bb_s0 + 2 * TILE * NHEADS);
    float*    zred   = (float*)(mask_s + MI);

    const int t    = threadIdx.x;
    const int lane = t & 31;
    const int wid  = t >> 5;
    const int rg   = wid & 3;
    const int hh   = wid >> 2;
    const int r0   = lane >> 2;
    const int c0   = lane & 3;

    const int row0 = (blockIdx.x >> 1) * MI;
    const int js   = blockIdx.x & 1;
    const int jb0  = js * KJ;

    const int rowA = row0 + rg * 16 + r0;
    const float2 aa0 = g_aa[(size_t)rowA * NHEADS + hh];
    const float2 aa1 = g_aa[(size_t)(rowA + 8) * NHEADS + hh];

    float acc[8][4];
#pragma unroll
    for (int n = 0; n < 8; n++)
#pragma unroll
        for (int q = 0; q < 4; q++) acc[n][q] = 0.f;
    float z0 = 0.f, z1 = 0.f;

    // per-thread staging roles (precomputed smem byte addresses)
    uint32_t hdst[4];
#pragma unroll
    for (int q = 0; q < 4; q++) {
        const int f = t + q * 512;            // float4 id 0..2047
        const int j = f >> 6;
        const int c = (f & 63) * 4;
        hdst[q] = (uint32_t)__cvta_generic_to_shared(&h_s0[j * HPAD + c]);
    }
    const uint32_t hbuf_b  = TILE * HPAD * 4;        // bytes per h buffer
    const uint32_t bbdst   = (uint32_t)__cvta_generic_to_shared(bb_s0) + t * 16;
    const uint32_t bbbuf_b = TILE * NHEADS * 8;

    // stage tile `tl` into buffer p
    auto stage = [&](int tl, int p) {
        const int jb = jb0 + tl * TILE;
        const float* src = g_h + (size_t)jb * CTOT;
#pragma unroll
        for (int q = 0; q < 4; q++)
            cp_async16(hdst[q] + p * hbuf_b, src + (t + q * 512) * 4);
        if (t < 64)
            cp_async16(bbdst + p * bbbuf_b, (const char*)(g_bb + (size_t)jb * NHEADS) + t * 16);
    };

    // adjacency prefetch: warp wid covers rows row0 + wid*4 .. +3
    const int mrow = row0 + wid * 4;
    int av[4];
#pragma unroll
    for (int rr = 0; rr < 4; rr++)
        av[rr] = adj[(size_t)(mrow + rr) * NN + jb0 + lane];

    stage(0, 0);
    asm volatile("cp.async.commit_group;");

    for (int tile = 0; tile < NTILES; tile++) {
        const int p = tile & 1;

        if (tile + 1 < NTILES) {
            stage(tile + 1, p ^ 1);
            asm volatile("cp.async.commit_group;");
            asm volatile("cp.async.wait_group 1;");
        } else {
            asm volatile("cp.async.wait_group 0;");
        }

        // masks for this tile + prefetch next adjacency
#pragma unroll
        for (int rr = 0; rr < 4; rr++) {
            unsigned m = __ballot_sync(0xffffffffu, av[rr] != 0);
            if (lane == 0) mask_s[wid * 4 + rr] = m;
        }
        if (tile + 1 < NTILES) {
            const int jbn = jb0 + (tile + 1) * TILE;
#pragma unroll
            for (int rr = 0; rr < 4; rr++)
                av[rr] = adj[(size_t)(mrow + rr) * NN + jbn + lane];
        }
        __syncthreads();

        const float*  hs = h_s0 + p * TILE * HPAD;
        const float2* bs = bb_s0 + p * TILE * NHEADS;
        const unsigned mw0 = mask_s[rg * 16 + r0];
        const unsigned mw1 = mask_s[rg * 16 + r0 + 8];

#pragma unroll
        for (int kc = 0; kc < 4; kc++) {
            const int jl0 = kc * 8 + c0;
            const int jl1 = jl0 + 4;
            const float2 bb0 = bs[jl0 * NHEADS + hh];
            const float2 bb1 = bs[jl1 * NHEADS + hh];

            float w0 = fmaxf(aa0.x * bb0.x, aa0.y * bb0.y);
            float w1 = fmaxf(aa1.x * bb0.x, aa1.y * bb0.y);
            float w2 = fmaxf(aa0.x * bb1.x, aa0.y * bb1.y);
            float w3 = fmaxf(aa1.x * bb1.x, aa1.y * bb1.y);
            if (!((mw0 >> jl0) & 1u)) w0 = 0.f;
            if (!((mw1 >> jl0) & 1u)) w1 = 0.f;
            if (!((mw0 >> jl1) & 1u)) w2 = 0.f;
            if (!((mw1 >> jl1) & 1u)) w3 = 0.f;
            z0 += w0 + w2;
            z1 += w1 + w3;

            unsigned afr[4];
            afr[0] = to_tf32(w0);
            afr[1] = to_tf32(w1);
            afr[2] = to_tf32(w2);
            afr[3] = to_tf32(w3);

#pragma unroll
            for (int nt = 0; nt < 8; nt++) {
                const int n0 = hh * 64 + nt * 8 + r0;
                const unsigned b0 = __float_as_uint(hs[jl0 * HPAD + n0]);
                const unsigned b1 = __float_as_uint(hs[jl1 * HPAD + n0]);
                mma_tf32(acc[nt], afr, b0, b1);
            }
        }
        __syncthreads();   // compute done before buffer p is restaged
    }

    // Z: reduce across the 4 lanes sharing a row
#pragma unroll
    for (int o = 1; o <= 2; o <<= 1) {
        z0 += __shfl_xor_sync(0xffffffffu, z0, o);
        z1 += __shfl_xor_sync(0xffffffffu, z1, o);
    }
    if (c0 == 0) {
        zred[(rg * 16 + r0) * NHEADS + hh]     = z0;
        zred[(rg * 16 + r0 + 8) * NHEADS + hh] = z1;
    }
    __syncthreads();
    if (t < MI * NHEADS)
        g_zpart[js][row0 + (t >> 2)][t & 3] = zred[t];

    // numerator partials straight from accumulators
#pragma unroll
    for (int nt = 0; nt < 8; nt++) {
        const int cb = hh * 64 + nt * 8 + 2 * c0;
        *(float2*)&g_part[js][rowA][cb]     = make_float2(acc[nt][0], acc[nt][1]);
        *(float2*)&g_part[js][rowA + 8][cb] = make_float2(acc[nt][2], acc[nt][3]);
    }
}

// ---------------------------------------------------------------------------
// Kernel 3: combine j-splits, normalize by Z, mean over heads.
// ---------------------------------------------------------------------------
__global__ __launch_bounds__(256) void k_final(float* __restrict__ out)
{
    const int idx = blockIdx.x * 256 + threadIdx.x;   // row*64 + f
    const int row = idx >> 6;
    const int f   = idx & 63;
    float o = 0.f;
#pragma unroll
    for (int h = 0; h < NHEADS; h++) {
        const float num = g_part[0][row][h * 64 + f] + g_part[1][row][h * 64 + f];
        const float zz  = g_zpart[0][row][h] + g_zpart[1][row][h];
        o += num / zz;
    }
    out[idx] = 0.25f * o;
}

// ---------------------------------------------------------------------------
extern "C" void kernel_launch(void* const* d_in, const int* in_sizes, int n_in,
                              void* d_out, int out_size)
{
    const float* x   = (const float*)d_in[0];   // 4096 x 256
    const int*   adj = (const int*)  d_in[1];   // 4096 x 4096
    const float* W   = (const float*)d_in[2];   // 256 x 256
    const float* a   = (const float*)d_in[3];   // 128 x 1
    float* out = (float*)d_out;                 // 4096 x 64

    (void)in_sizes; (void)n_in; (void)out_size;

    const int smem_attn = (2 * TILE * HPAD) * 4          // h_s
                        + (2 * TILE * NHEADS) * 8        // bb_s
                        + MI * 4                         // masks
                        + MI * NHEADS * 4;               // zred
    static int attr_done = 0;
    // (idempotent host-side attribute; legal during capture, same every call)
    cudaFuncSetAttribute(k_attn, cudaFuncAttributeMaxDynamicSharedMemorySize,
                         smem_attn);
    (void)attr_done;

    k_proj<<<NN / 8, 256>>>(x, W, a);
    k_gmax<<<1, 256>>>();
    k_prep<<<NN * NHEADS / 256, 256>>>();
    k_attn<<<(NN / MI) * SJ, 512, smem_attn>>>(adj);
    k_final<<<NN * FOUT_ / 256, 256>>>(out);
}